// round 1
// baseline (speedup 1.0000x reference)
#include <cuda_runtime.h>
#include <cstdint>

#define Bn_ 4
#define Hh 64
#define Ww_ 64
#define Lseq 4096
#define DM 96
#define DI 96
#define DS 16
#define Kdir 4
#define DTR 6
#define CDIM 38   // DTR + 2*DS

// -------------------- scratch (static device arrays; no allocs) --------------------
__device__ float g_xz[Bn_ * Lseq * 192];          // in_proj output [b][p][192]
__device__ float g_xraw[Bn_ * DI * Lseq];         // pre-conv, channel-major [b][d][p]
__device__ float g_xc[Bn_ * DI * Lseq];           // conv+silu, hw order
__device__ float g_xcT[Bn_ * DI * Lseq];          // conv+silu, wh order (plane transpose)
__device__ float g_xdbl[16 * Lseq * CDIM];        // [bk][l][38] = dts(6)|B(16)|C(16)
__device__ float g_delta[16 * Lseq * DI];         // [bk][l][96]
__device__ float g_ys[16 * Lseq * DI];            // scan output [bk][l][96]
__device__ float g_yg[Bn_ * Lseq * DI];           // post-LN gated [b][p][96]

// -------------------- generic C = A * B^T GEMM (fp32, 64x64 tiles) --------------------
__global__ void gemm_abt(const float* __restrict__ A, const float* __restrict__ Bm,
                         float* __restrict__ C, int M, int N, int K) {
    __shared__ __align__(16) float As[32][68];
    __shared__ __align__(16) float Bs[32][68];
    int tid = threadIdx.x;                 // 256 threads
    int tx = tid & 15, ty = tid >> 4;      // 16 x 16
    int rowBase = blockIdx.y * 64;
    int colBase = blockIdx.x * 64;
    float acc[4][4];
#pragma unroll
    for (int i = 0; i < 4; i++)
#pragma unroll
        for (int j = 0; j < 4; j++) acc[i][j] = 0.f;

    for (int k0 = 0; k0 < K; k0 += 32) {
#pragma unroll
        for (int pass = 0; pass < 8; pass++) {
            int m = (tid >> 5) + pass * 8;   // 0..63
            int kk = tid & 31;
            As[kk][m] = A[(size_t)(rowBase + m) * K + k0 + kk];
            int nn = colBase + m;
            Bs[kk][m] = (nn < N) ? Bm[(size_t)nn * K + k0 + kk] : 0.f;
        }
        __syncthreads();
#pragma unroll
        for (int kk = 0; kk < 32; kk++) {
            float4 a4 = *reinterpret_cast<const float4*>(&As[kk][ty * 4]);
            float4 b4 = *reinterpret_cast<const float4*>(&Bs[kk][tx * 4]);
            float av[4] = {a4.x, a4.y, a4.z, a4.w};
            float bv[4] = {b4.x, b4.y, b4.z, b4.w};
#pragma unroll
            for (int i = 0; i < 4; i++)
#pragma unroll
                for (int j = 0; j < 4; j++) acc[i][j] = fmaf(av[i], bv[j], acc[i][j]);
        }
        __syncthreads();
    }
    int col = colBase + tx * 4;
    if (col < N) {
#pragma unroll
        for (int i = 0; i < 4; i++) {
            int row = rowBase + ty * 4 + i;
            float4 o = make_float4(acc[i][0], acc[i][1], acc[i][2], acc[i][3]);
            *reinterpret_cast<float4*>(&C[(size_t)row * N + col]) = o;
        }
    }
}

// -------------------- split + transpose: xraw[b][d][p] = xz[b][p][d], d<96 --------------------
__global__ void split_transpose(const float* __restrict__ xz, float* __restrict__ xraw) {
    __shared__ float s[32][33];
    int b = blockIdx.z;
    int p0 = blockIdx.x * 32;
    int d0 = blockIdx.y * 32;
    int tid = threadIdx.x;
#pragma unroll
    for (int pass = 0; pass < 4; pass++) {
        int py = (tid >> 5) + pass * 8;
        int dx = tid & 31;
        s[py][dx] = xz[((size_t)b * Lseq + p0 + py) * 192 + d0 + dx];
    }
    __syncthreads();
#pragma unroll
    for (int pass = 0; pass < 4; pass++) {
        int dy = (tid >> 5) + pass * 8;
        int px = tid & 31;
        xraw[((size_t)b * DI + d0 + dy) * Lseq + p0 + px] = s[px][dy];
    }
}

// -------------------- depthwise conv3x3 + SiLU, write hw and wh orders --------------------
__global__ void conv_silu(const float* __restrict__ xraw, const float* __restrict__ cw,
                          const float* __restrict__ cb, float* __restrict__ xc,
                          float* __restrict__ xcT) {
    __shared__ float sin_[64][65];
    __shared__ float sout[64][65];
    int bd = blockIdx.x;              // b*96+d
    int d = bd % DI;
    const float* plane = xraw + (size_t)bd * Lseq;
    int tid = threadIdx.x;            // 256
    for (int i = tid; i < 4096; i += 256) sin_[i >> 6][i & 63] = plane[i];
    float w9[9];
#pragma unroll
    for (int j = 0; j < 9; j++) w9[j] = cw[d * 9 + j];
    float bias = cb[d];
    __syncthreads();
    for (int i = tid; i < 4096; i += 256) {
        int h = i >> 6, w = i & 63;
        float acc = bias;
#pragma unroll
        for (int di = -1; di <= 1; di++) {
#pragma unroll
            for (int dj = -1; dj <= 1; dj++) {
                int hh = h + di, ww = w + dj;
                if (hh >= 0 && hh < 64 && ww >= 0 && ww < 64)
                    acc = fmaf(w9[(di + 1) * 3 + dj + 1], sin_[hh][ww], acc);
            }
        }
        float s = acc / (1.f + __expf(-acc));
        sout[h][w] = s;
        xc[(size_t)bd * Lseq + i] = s;
    }
    __syncthreads();
    for (int i = tid; i < 4096; i += 256) {
        int w = i >> 6, h = i & 63;   // output index = w*64+h
        xcT[(size_t)bd * Lseq + i] = sout[h][w];
    }
}

// -------------------- x_proj: xdbl[bk][l][38] = W[k](38x96) @ u(96 x Ltile) --------------------
#define LT 64
__global__ void xproj_kernel(const float* __restrict__ xc, const float* __restrict__ xcT,
                             const float* __restrict__ xpw, float* __restrict__ xdbl) {
    __shared__ float Ws[CDIM * 96];       // 14.6 KB
    __shared__ float Us[96][LT];          // 24 KB
    int bk = blockIdx.y;
    int b = bk >> 2, k = bk & 3;
    int l0 = blockIdx.x * LT;
    int tid = threadIdx.x;                // 256
    for (int i = tid; i < CDIM * 96; i += 256) Ws[i] = xpw[k * CDIM * 96 + i];
    const float* src = ((k & 1) ? xcT : xc) + (size_t)b * DI * Lseq;
    bool rev = (k >= 2);
    for (int i = tid; i < 96 * LT; i += 256) {
        int e = i / LT, li = i % LT;
        int l = l0 + li;
        Us[e][li] = src[(size_t)e * Lseq + (rev ? (Lseq - 1 - l) : l)];
    }
    __syncthreads();
    int lx = tid & 31, cy = tid >> 5;     // cy 0..7
    float acc[5][2];
#pragma unroll
    for (int j = 0; j < 5; j++) { acc[j][0] = 0.f; acc[j][1] = 0.f; }
#pragma unroll 4
    for (int e = 0; e < 96; e++) {
        float u0 = Us[e][lx];
        float u1 = Us[e][lx + 32];
#pragma unroll
        for (int j = 0; j < 5; j++) {
            int c = cy + 8 * j;
            float w = (c < CDIM) ? Ws[c * 96 + e] : 0.f;
            acc[j][0] = fmaf(w, u0, acc[j][0]);
            acc[j][1] = fmaf(w, u1, acc[j][1]);
        }
    }
#pragma unroll
    for (int j = 0; j < 5; j++) {
        int c = cy + 8 * j;
        if (c < CDIM) {
            xdbl[((size_t)bk * Lseq + l0 + lx) * CDIM + c] = acc[j][0];
            xdbl[((size_t)bk * Lseq + l0 + lx + 32) * CDIM + c] = acc[j][1];
        }
    }
}

// -------------------- dt projection + softplus -> delta[bk][l][96] --------------------
__device__ __forceinline__ float softplusf(float x) {
    return (x > 15.f) ? x : log1pf(__expf(x));
}

__global__ void delta_kernel(const float* __restrict__ xdbl, const float* __restrict__ dtw,
                             const float* __restrict__ dtb, float* __restrict__ delta) {
    int idx = blockIdx.x * 256 + threadIdx.x;   // over 16*4096*96
    if (idx >= 16 * Lseq * DI) return;
    int d = idx % DI;
    int bl = idx / DI;                          // bk*4096 + l
    int bk = bl / Lseq;
    int k = bk & 3;
    const float* xr = xdbl + (size_t)bl * CDIM;
    const float* wr = dtw + (k * DI + d) * DTR;
    float acc = dtb[k * DI + d];
#pragma unroll
    for (int r = 0; r < DTR; r++) acc = fmaf(xr[r], wr[r], acc);
    delta[idx] = softplusf(acc);
}

// -------------------- selective scan: warp = 2 d x 16 n --------------------
__global__ void scan_kernel(const float* __restrict__ delta, const float* __restrict__ xdbl,
                            const float* __restrict__ xc, const float* __restrict__ xcT,
                            const float* __restrict__ A_logs, const float* __restrict__ Dsp,
                            float* __restrict__ ys) {
    int w = blockIdx.x * 8 + (threadIdx.x >> 5);  // 768 warps
    int lane = threadIdx.x & 31;
    int bk = w / 48;
    int dp = w % 48;
    int b = bk >> 2, k = bk & 3;
    int n = lane & 15;
    int d = dp * 2 + (lane >> 4);
    float Aval = -__expf(A_logs[(k * DI + d) * DS + n]);
    float Dval = Dsp[k * DI + d];
    const float* usrc = (((k & 1) ? xcT : xc) + ((size_t)b * DI + d) * Lseq);
    const float* drow = delta + (size_t)bk * Lseq * DI + d;
    const float* xrow = xdbl + (size_t)bk * Lseq * CDIM;
    float* yrow = ys + (size_t)bk * Lseq * DI + d;
    bool rev = (k >= 2);
    bool writer = (n == 0);
    float h = 0.f;
#pragma unroll 4
    for (int l = 0; l < Lseq; l++) {
        float dl = __ldg(drow + (size_t)l * DI);
        float uu = __ldg(usrc + (rev ? (Lseq - 1 - l) : l));
        float Bv = __ldg(xrow + (size_t)l * CDIM + DTR + n);
        float Cv = __ldg(xrow + (size_t)l * CDIM + DTR + DS + n);
        float dA = __expf(dl * Aval);
        h = fmaf(h, dA, dl * uu * Bv);
        float yv = h * Cv;
        yv += __shfl_xor_sync(0xffffffffu, yv, 8);
        yv += __shfl_xor_sync(0xffffffffu, yv, 4);
        yv += __shfl_xor_sync(0xffffffffu, yv, 2);
        yv += __shfl_xor_sync(0xffffffffu, yv, 1);
        if (writer) yrow[(size_t)l * DI] = fmaf(Dval, uu, yv);
    }
}

// -------------------- combine 4 directions + LayerNorm + SiLU gate --------------------
__global__ void combine_kernel(const float* __restrict__ ys, const float* __restrict__ xz,
                               const float* __restrict__ nw, const float* __restrict__ nb,
                               float* __restrict__ yg) {
    int ty = threadIdx.y;                        // 0..1
    int pp = blockIdx.x * 2 + ty;                // over B*L/2 blocks * 2
    int b = pp / Lseq, p = pp % Lseq;
    int d = threadIdx.x;                         // 0..95
    int hq = p >> 6, wq = p & 63;
    int q = wq * 64 + hq;
    const float* base = ys + (size_t)(b * 4) * Lseq * DI;
    float v = base[((size_t)0 * Lseq + p) * DI + d]
            + base[((size_t)1 * Lseq + q) * DI + d]
            + base[((size_t)2 * Lseq + (Lseq - 1 - p)) * DI + d]
            + base[((size_t)3 * Lseq + (Lseq - 1 - q)) * DI + d];
    __shared__ float red[2][6];
    float s1 = v, s2 = v * v;
#pragma unroll
    for (int o = 16; o >= 1; o >>= 1) {
        s1 += __shfl_xor_sync(0xffffffffu, s1, o);
        s2 += __shfl_xor_sync(0xffffffffu, s2, o);
    }
    if ((d & 31) == 0) {
        red[ty][d >> 5] = s1;
        red[ty][3 + (d >> 5)] = s2;
    }
    __syncthreads();
    float S1 = red[ty][0] + red[ty][1] + red[ty][2];
    float S2 = red[ty][3] + red[ty][4] + red[ty][5];
    float mu = S1 * (1.f / 96.f);
    float var = S2 * (1.f / 96.f) - mu * mu;
    float yn = (v - mu) * rsqrtf(var + 1e-5f) * nw[d] + nb[d];
    float zv = xz[((size_t)b * Lseq + p) * 192 + 96 + d];
    yg[((size_t)b * Lseq + p) * DI + d] = yn * (zv / (1.f + __expf(-zv)));
}

// -------------------- host launcher --------------------
extern "C" void kernel_launch(void* const* d_in, const int* in_sizes, int n_in,
                              void* d_out, int out_size) {
    const float* x     = (const float*)d_in[0];
    const float* inw   = (const float*)d_in[1];
    const float* convw = (const float*)d_in[2];
    const float* convb = (const float*)d_in[3];
    const float* xpw   = (const float*)d_in[4];
    const float* dtw   = (const float*)d_in[5];
    const float* dtb   = (const float*)d_in[6];
    const float* alog  = (const float*)d_in[7];
    const float* dsp   = (const float*)d_in[8];
    const float* nw    = (const float*)d_in[9];
    const float* nb    = (const float*)d_in[10];
    const float* ow    = (const float*)d_in[11];
    float* out = (float*)d_out;

    float *xz, *xraw, *xc, *xcT, *xdbl, *delta, *ys, *yg;
    cudaGetSymbolAddress((void**)&xz, g_xz);
    cudaGetSymbolAddress((void**)&xraw, g_xraw);
    cudaGetSymbolAddress((void**)&xc, g_xc);
    cudaGetSymbolAddress((void**)&xcT, g_xcT);
    cudaGetSymbolAddress((void**)&xdbl, g_xdbl);
    cudaGetSymbolAddress((void**)&delta, g_delta);
    cudaGetSymbolAddress((void**)&ys, g_ys);
    cudaGetSymbolAddress((void**)&yg, g_yg);

    // 1. in_proj: xz[16384][192] = x[16384][96] @ inw^T
    gemm_abt<<<dim3(3, 256), 256>>>(x, inw, xz, Bn_ * Lseq, 192, 96);
    // 2. split + transpose to channel-major
    split_transpose<<<dim3(Lseq / 32, 3, Bn_), 256>>>(xz, xraw);
    // 3. depthwise conv + SiLU, produce hw + wh orderings
    conv_silu<<<Bn_ * DI, 256>>>(xraw, convw, convb, xc, xcT);
    // 4. x_proj -> xdbl
    xproj_kernel<<<dim3(Lseq / LT, 16), 256>>>(xc, xcT, xpw, xdbl);
    // 5. dt proj + softplus -> delta
    delta_kernel<<<(16 * Lseq * DI) / 256, 256>>>(xdbl, dtw, dtb, delta);
    // 6. selective scan
    scan_kernel<<<96, 256>>>(delta, xdbl, xc, xcT, alog, dsp, ys);
    // 7. combine + LN + gate
    combine_kernel<<<(Bn_ * Lseq) / 2, dim3(96, 2)>>>(ys, xz, nw, nb, yg);
    // 8. out_proj
    gemm_abt<<<dim3(2, 256), 256>>>(yg, ow, out, Bn_ * Lseq, 96, 96);
}

// round 2
// speedup vs baseline: 3.6908x; 3.6908x over previous
#include <cuda_runtime.h>
#include <cstdint>

#define Bn_ 4
#define Hh 64
#define Ww_ 64
#define Lseq 4096
#define DM 96
#define DI 96
#define DS 16
#define Kdir 4
#define DTR 6
#define CDIM 38   // DTR + 2*DS
#define CH 64
#define NCH (Lseq / CH)        // 64
#define NCHAIN 24576           // 16 * 96 * 16  (bk, d, n)

// -------------------- scratch (static device arrays; no allocs) --------------------
__device__ float g_xz[Bn_ * Lseq * 192];          // in_proj output [b][p][192]
__device__ float g_xraw[Bn_ * DI * Lseq];         // pre-conv, channel-major [b][d][p]
__device__ float g_xc[Bn_ * DI * Lseq];           // conv+silu, hw order
__device__ float g_xcT[Bn_ * DI * Lseq];          // conv+silu, wh order (plane transpose)
__device__ float g_xdbl[16 * Lseq * CDIM];        // [bk][l][38] = dts(6)|B(16)|C(16)
__device__ float g_delta[16 * Lseq * DI];         // [bk][l][96]
__device__ float g_ys[16 * Lseq * DI];            // scan output [bk][l][96]
__device__ float g_yg[Bn_ * Lseq * DI];           // post-LN gated [b][p][96]
__device__ float g_hend[NCH * NCHAIN];            // per-chunk local scan end
__device__ float g_pprod[NCH * NCHAIN];           // per-chunk dA product
__device__ float g_hinit[NCH * NCHAIN];           // per-chunk initial state

// -------------------- generic C = A * B^T GEMM (fp32, 64x64 tiles) --------------------
__global__ void gemm_abt(const float* __restrict__ A, const float* __restrict__ Bm,
                         float* __restrict__ C, int M, int N, int K) {
    __shared__ __align__(16) float As[32][68];
    __shared__ __align__(16) float Bs[32][68];
    int tid = threadIdx.x;                 // 256 threads
    int tx = tid & 15, ty = tid >> 4;      // 16 x 16
    int rowBase = blockIdx.y * 64;
    int colBase = blockIdx.x * 64;
    float acc[4][4];
#pragma unroll
    for (int i = 0; i < 4; i++)
#pragma unroll
        for (int j = 0; j < 4; j++) acc[i][j] = 0.f;

    for (int k0 = 0; k0 < K; k0 += 32) {
#pragma unroll
        for (int pass = 0; pass < 8; pass++) {
            int m = (tid >> 5) + pass * 8;   // 0..63
            int kk = tid & 31;
            As[kk][m] = A[(size_t)(rowBase + m) * K + k0 + kk];
            int nn = colBase + m;
            Bs[kk][m] = (nn < N) ? Bm[(size_t)nn * K + k0 + kk] : 0.f;
        }
        __syncthreads();
#pragma unroll
        for (int kk = 0; kk < 32; kk++) {
            float4 a4 = *reinterpret_cast<const float4*>(&As[kk][ty * 4]);
            float4 b4 = *reinterpret_cast<const float4*>(&Bs[kk][tx * 4]);
            float av[4] = {a4.x, a4.y, a4.z, a4.w};
            float bv[4] = {b4.x, b4.y, b4.z, b4.w};
#pragma unroll
            for (int i = 0; i < 4; i++)
#pragma unroll
                for (int j = 0; j < 4; j++) acc[i][j] = fmaf(av[i], bv[j], acc[i][j]);
        }
        __syncthreads();
    }
    int col = colBase + tx * 4;
    if (col < N) {
#pragma unroll
        for (int i = 0; i < 4; i++) {
            int row = rowBase + ty * 4 + i;
            float4 o = make_float4(acc[i][0], acc[i][1], acc[i][2], acc[i][3]);
            *reinterpret_cast<float4*>(&C[(size_t)row * N + col]) = o;
        }
    }
}

// -------------------- split + transpose: xraw[b][d][p] = xz[b][p][d], d<96 --------------------
__global__ void split_transpose(const float* __restrict__ xz, float* __restrict__ xraw) {
    __shared__ float s[32][33];
    int b = blockIdx.z;
    int p0 = blockIdx.x * 32;
    int d0 = blockIdx.y * 32;
    int tid = threadIdx.x;
#pragma unroll
    for (int pass = 0; pass < 4; pass++) {
        int py = (tid >> 5) + pass * 8;
        int dx = tid & 31;
        s[py][dx] = xz[((size_t)b * Lseq + p0 + py) * 192 + d0 + dx];
    }
    __syncthreads();
#pragma unroll
    for (int pass = 0; pass < 4; pass++) {
        int dy = (tid >> 5) + pass * 8;
        int px = tid & 31;
        xraw[((size_t)b * DI + d0 + dy) * Lseq + p0 + px] = s[px][dy];
    }
}

// -------------------- depthwise conv3x3 + SiLU, write hw and wh orders --------------------
__global__ void conv_silu(const float* __restrict__ xraw, const float* __restrict__ cw,
                          const float* __restrict__ cb, float* __restrict__ xc,
                          float* __restrict__ xcT) {
    __shared__ float sin_[64][65];
    __shared__ float sout[64][65];
    int bd = blockIdx.x;              // b*96+d
    int d = bd % DI;
    const float* plane = xraw + (size_t)bd * Lseq;
    int tid = threadIdx.x;            // 256
    for (int i = tid; i < 4096; i += 256) sin_[i >> 6][i & 63] = plane[i];
    float w9[9];
#pragma unroll
    for (int j = 0; j < 9; j++) w9[j] = cw[d * 9 + j];
    float bias = cb[d];
    __syncthreads();
    for (int i = tid; i < 4096; i += 256) {
        int h = i >> 6, w = i & 63;
        float acc = bias;
#pragma unroll
        for (int di = -1; di <= 1; di++) {
#pragma unroll
            for (int dj = -1; dj <= 1; dj++) {
                int hh = h + di, ww = w + dj;
                if (hh >= 0 && hh < 64 && ww >= 0 && ww < 64)
                    acc = fmaf(w9[(di + 1) * 3 + dj + 1], sin_[hh][ww], acc);
            }
        }
        float s = acc / (1.f + __expf(-acc));
        sout[h][w] = s;
        xc[(size_t)bd * Lseq + i] = s;
    }
    __syncthreads();
    for (int i = tid; i < 4096; i += 256) {
        int w = i >> 6, h = i & 63;   // output index = w*64+h
        xcT[(size_t)bd * Lseq + i] = sout[h][w];
    }
}

// -------------------- x_proj: xdbl[bk][l][38] = W[k](38x96) @ u(96 x Ltile) --------------------
#define LT 64
__global__ void xproj_kernel(const float* __restrict__ xc, const float* __restrict__ xcT,
                             const float* __restrict__ xpw, float* __restrict__ xdbl) {
    __shared__ float Ws[CDIM * 96];       // 14.6 KB
    __shared__ float Us[96][LT];          // 24 KB
    int bk = blockIdx.y;
    int b = bk >> 2, k = bk & 3;
    int l0 = blockIdx.x * LT;
    int tid = threadIdx.x;                // 256
    for (int i = tid; i < CDIM * 96; i += 256) Ws[i] = xpw[k * CDIM * 96 + i];
    const float* src = ((k & 1) ? xcT : xc) + (size_t)b * DI * Lseq;
    bool rev = (k >= 2);
    for (int i = tid; i < 96 * LT; i += 256) {
        int e = i / LT, li = i % LT;
        int l = l0 + li;
        Us[e][li] = src[(size_t)e * Lseq + (rev ? (Lseq - 1 - l) : l)];
    }
    __syncthreads();
    int lx = tid & 31, cy = tid >> 5;     // cy 0..7
    float acc[5][2];
#pragma unroll
    for (int j = 0; j < 5; j++) { acc[j][0] = 0.f; acc[j][1] = 0.f; }
#pragma unroll 4
    for (int e = 0; e < 96; e++) {
        float u0 = Us[e][lx];
        float u1 = Us[e][lx + 32];
#pragma unroll
        for (int j = 0; j < 5; j++) {
            int c = cy + 8 * j;
            float w = (c < CDIM) ? Ws[c * 96 + e] : 0.f;
            acc[j][0] = fmaf(w, u0, acc[j][0]);
            acc[j][1] = fmaf(w, u1, acc[j][1]);
        }
    }
#pragma unroll
    for (int j = 0; j < 5; j++) {
        int c = cy + 8 * j;
        if (c < CDIM) {
            xdbl[((size_t)bk * Lseq + l0 + lx) * CDIM + c] = acc[j][0];
            xdbl[((size_t)bk * Lseq + l0 + lx + 32) * CDIM + c] = acc[j][1];
        }
    }
}

// -------------------- dt projection + softplus -> delta[bk][l][96] --------------------
__device__ __forceinline__ float softplusf(float x) {
    return (x > 15.f) ? x : log1pf(__expf(x));
}

__global__ void delta_kernel(const float* __restrict__ xdbl, const float* __restrict__ dtw,
                             const float* __restrict__ dtb, float* __restrict__ delta) {
    int idx = blockIdx.x * 256 + threadIdx.x;   // over 16*4096*96
    if (idx >= 16 * Lseq * DI) return;
    int d = idx % DI;
    int bl = idx / DI;                          // bk*4096 + l
    int bk = bl / Lseq;
    int k = bk & 3;
    const float* xr = xdbl + (size_t)bl * CDIM;
    const float* wr = dtw + (k * DI + d) * DTR;
    float acc = dtb[k * DI + d];
#pragma unroll
    for (int r = 0; r < DTR; r++) acc = fmaf(xr[r], wr[r], acc);
    delta[idx] = softplusf(acc);
}

// -------------------- chunked selective scan --------------------
// chain = bk*1536 + dp*32 + lane  (lane = hi*16 + n, d = dp*2 + hi)
// storage layout: [chunk][chain]

// Phase A: local scan from h=0, accumulate dA-product P
__global__ void scanA_kernel(const float* __restrict__ delta, const float* __restrict__ xdbl,
                             const float* __restrict__ xc, const float* __restrict__ xcT,
                             const float* __restrict__ A_logs,
                             float* __restrict__ hend, float* __restrict__ pprod) {
    int w = blockIdx.x * 8 + (threadIdx.x >> 5);   // 49152 warps
    int lane = threadIdx.x & 31;
    int bk = w / (48 * NCH);
    int rem = w % (48 * NCH);
    int chunk = rem / 48;
    int dp = rem % 48;
    int b = bk >> 2, k = bk & 3;
    int n = lane & 15;
    int d = dp * 2 + (lane >> 4);
    float Aval = -__expf(A_logs[(k * DI + d) * DS + n]);
    bool rev = (k >= 2);
    int l0 = chunk * CH;

    const float* drow = delta + ((size_t)bk * Lseq + l0) * DI + d;
    const float* xrow = xdbl + ((size_t)bk * Lseq + l0) * CDIM + DTR + n;
    const float* ubase = ((k & 1) ? xcT : xc) + ((size_t)b * DI + d) * Lseq;
    const float* urow = ubase + (rev ? (Lseq - 1 - l0) : l0);
    int ustep = rev ? -1 : 1;

    float h = 0.f, P = 1.f;
#pragma unroll 8
    for (int i = 0; i < CH; i++) {
        float dl = __ldg(drow);
        float uu = __ldg(urow);
        float Bv = __ldg(xrow);
        float dA = __expf(dl * Aval);
        P *= dA;
        h = fmaf(h, dA, dl * uu * Bv);
        drow += DI;
        xrow += CDIM;
        urow += ustep;
    }
    int cidx = chunk * NCHAIN + bk * 1536 + dp * 32 + lane;
    hend[cidx] = h;
    pprod[cidx] = P;
}

// Phase B: serial prefix across chunks (per chain)
__global__ void scanB_kernel(const float* __restrict__ hend, const float* __restrict__ pprod,
                             float* __restrict__ hinit) {
    int chain = blockIdx.x * 256 + threadIdx.x;    // 24576 chains
    float H = 0.f;
#pragma unroll 8
    for (int c = 0; c < NCH; c++) {
        int idx = c * NCHAIN + chain;
        hinit[idx] = H;
        H = fmaf(H, pprod[idx], hend[idx]);
    }
}

// Phase C: recompute local scan with correct init; produce y
__global__ void scanC_kernel(const float* __restrict__ delta, const float* __restrict__ xdbl,
                             const float* __restrict__ xc, const float* __restrict__ xcT,
                             const float* __restrict__ A_logs, const float* __restrict__ Dsp,
                             const float* __restrict__ hinit, float* __restrict__ ys) {
    int w = blockIdx.x * 8 + (threadIdx.x >> 5);
    int lane = threadIdx.x & 31;
    int bk = w / (48 * NCH);
    int rem = w % (48 * NCH);
    int chunk = rem / 48;
    int dp = rem % 48;
    int b = bk >> 2, k = bk & 3;
    int n = lane & 15;
    int d = dp * 2 + (lane >> 4);
    float Aval = -__expf(A_logs[(k * DI + d) * DS + n]);
    float Dval = Dsp[k * DI + d];
    bool rev = (k >= 2);
    int l0 = chunk * CH;

    const float* drow = delta + ((size_t)bk * Lseq + l0) * DI + d;
    const float* xrow = xdbl + ((size_t)bk * Lseq + l0) * CDIM + DTR + n;
    const float* ubase = ((k & 1) ? xcT : xc) + ((size_t)b * DI + d) * Lseq;
    const float* urow = ubase + (rev ? (Lseq - 1 - l0) : l0);
    int ustep = rev ? -1 : 1;
    float* yrow = ys + ((size_t)bk * Lseq + l0) * DI + d;
    bool writer = (n == 0);

    float h = hinit[chunk * NCHAIN + bk * 1536 + dp * 32 + lane];
#pragma unroll 4
    for (int i = 0; i < CH; i++) {
        float dl = __ldg(drow);
        float uu = __ldg(urow);
        float Bv = __ldg(xrow);
        float Cv = __ldg(xrow + DS);
        float dA = __expf(dl * Aval);
        h = fmaf(h, dA, dl * uu * Bv);
        float yv = h * Cv;
        yv += __shfl_xor_sync(0xffffffffu, yv, 8);
        yv += __shfl_xor_sync(0xffffffffu, yv, 4);
        yv += __shfl_xor_sync(0xffffffffu, yv, 2);
        yv += __shfl_xor_sync(0xffffffffu, yv, 1);
        if (writer) *yrow = fmaf(Dval, uu, yv);
        drow += DI;
        xrow += CDIM;
        urow += ustep;
        yrow += DI;
    }
}

// -------------------- combine 4 directions + LayerNorm + SiLU gate --------------------
__global__ void combine_kernel(const float* __restrict__ ys, const float* __restrict__ xz,
                               const float* __restrict__ nw, const float* __restrict__ nb,
                               float* __restrict__ yg) {
    int ty = threadIdx.y;                        // 0..1
    int pp = blockIdx.x * 2 + ty;                // over B*L/2 blocks * 2
    int b = pp / Lseq, p = pp % Lseq;
    int d = threadIdx.x;                         // 0..95
    int hq = p >> 6, wq = p & 63;
    int q = wq * 64 + hq;
    const float* base = ys + (size_t)(b * 4) * Lseq * DI;
    float v = base[((size_t)0 * Lseq + p) * DI + d]
            + base[((size_t)1 * Lseq + q) * DI + d]
            + base[((size_t)2 * Lseq + (Lseq - 1 - p)) * DI + d]
            + base[((size_t)3 * Lseq + (Lseq - 1 - q)) * DI + d];
    __shared__ float red[2][6];
    float s1 = v, s2 = v * v;
#pragma unroll
    for (int o = 16; o >= 1; o >>= 1) {
        s1 += __shfl_xor_sync(0xffffffffu, s1, o);
        s2 += __shfl_xor_sync(0xffffffffu, s2, o);
    }
    if ((d & 31) == 0) {
        red[ty][d >> 5] = s1;
        red[ty][3 + (d >> 5)] = s2;
    }
    __syncthreads();
    float S1 = red[ty][0] + red[ty][1] + red[ty][2];
    float S2 = red[ty][3] + red[ty][4] + red[ty][5];
    float mu = S1 * (1.f / 96.f);
    float var = S2 * (1.f / 96.f) - mu * mu;
    float yn = (v - mu) * rsqrtf(var + 1e-5f) * nw[d] + nb[d];
    float zv = xz[((size_t)b * Lseq + p) * 192 + 96 + d];
    yg[((size_t)b * Lseq + p) * DI + d] = yn * (zv / (1.f + __expf(-zv)));
}

// -------------------- host launcher --------------------
extern "C" void kernel_launch(void* const* d_in, const int* in_sizes, int n_in,
                              void* d_out, int out_size) {
    const float* x     = (const float*)d_in[0];
    const float* inw   = (const float*)d_in[1];
    const float* convw = (const float*)d_in[2];
    const float* convb = (const float*)d_in[3];
    const float* xpw   = (const float*)d_in[4];
    const float* dtw   = (const float*)d_in[5];
    const float* dtb   = (const float*)d_in[6];
    const float* alog  = (const float*)d_in[7];
    const float* dsp   = (const float*)d_in[8];
    const float* nw    = (const float*)d_in[9];
    const float* nb    = (const float*)d_in[10];
    const float* ow    = (const float*)d_in[11];
    float* out = (float*)d_out;

    float *xz, *xraw, *xc, *xcT, *xdbl, *delta, *ys, *yg, *hend, *pprod, *hinit;
    cudaGetSymbolAddress((void**)&xz, g_xz);
    cudaGetSymbolAddress((void**)&xraw, g_xraw);
    cudaGetSymbolAddress((void**)&xc, g_xc);
    cudaGetSymbolAddress((void**)&xcT, g_xcT);
    cudaGetSymbolAddress((void**)&xdbl, g_xdbl);
    cudaGetSymbolAddress((void**)&delta, g_delta);
    cudaGetSymbolAddress((void**)&ys, g_ys);
    cudaGetSymbolAddress((void**)&yg, g_yg);
    cudaGetSymbolAddress((void**)&hend, g_hend);
    cudaGetSymbolAddress((void**)&pprod, g_pprod);
    cudaGetSymbolAddress((void**)&hinit, g_hinit);

    // 1. in_proj: xz[16384][192] = x[16384][96] @ inw^T
    gemm_abt<<<dim3(3, 256), 256>>>(x, inw, xz, Bn_ * Lseq, 192, 96);
    // 2. split + transpose to channel-major
    split_transpose<<<dim3(Lseq / 32, 3, Bn_), 256>>>(xz, xraw);
    // 3. depthwise conv + SiLU, produce hw + wh orderings
    conv_silu<<<Bn_ * DI, 256>>>(xraw, convw, convb, xc, xcT);
    // 4. x_proj -> xdbl
    xproj_kernel<<<dim3(Lseq / LT, 16), 256>>>(xc, xcT, xpw, xdbl);
    // 5. dt proj + softplus -> delta
    delta_kernel<<<(16 * Lseq * DI) / 256, 256>>>(xdbl, dtw, dtb, delta);
    // 6. chunked selective scan (3 phases)
    scanA_kernel<<<16 * 48 * NCH / 8, 256>>>(delta, xdbl, xc, xcT, alog, hend, pprod);
    scanB_kernel<<<NCHAIN / 256, 256>>>(hend, pprod, hinit);
    scanC_kernel<<<16 * 48 * NCH / 8, 256>>>(delta, xdbl, xc, xcT, alog, dsp, hinit, ys);
    // 7. combine + LN + gate
    combine_kernel<<<(Bn_ * Lseq) / 2, dim3(96, 2)>>>(ys, xz, nw, nb, yg);
    // 8. out_proj
    gemm_abt<<<dim3(2, 256), 256>>>(yg, ow, out, Bn_ * Lseq, 96, 96);
}

// round 3
// speedup vs baseline: 3.7297x; 1.0105x over previous
#include <cuda_runtime.h>
#include <cstdint>

#define Bn_ 4
#define Lseq 4096
#define DM 96
#define DI 96
#define DS 16
#define DTR 6
#define CDIM 38
#define BCW 32                 // packed B|C row width
#define CH 64
#define NCH (Lseq / CH)        // 64
#define NCHAIN 24576           // 16 * 96 * 16

// -------------------- scratch --------------------
__device__ float g_xz[Bn_ * Lseq * 192];
__device__ float g_xraw[Bn_ * DI * Lseq];
__device__ float g_xc[Bn_ * DI * Lseq];
__device__ float g_xcT[Bn_ * DI * Lseq];
__device__ float g_xbc[16 * Lseq * BCW];          // [bk][l][32] = B(16)|C(16)
__device__ float g_deltaT[16 * DI * Lseq];        // [bk][d][l]
__device__ float g_ysd[16 * DI * Lseq];           // scan out [bk][d][p] (spatial hw order)
__device__ float g_ycomb[Bn_ * Lseq * DI];        // combined [b][p][d]
__device__ float g_yg[Bn_ * Lseq * DI];
__device__ float g_hend[NCH * NCHAIN];
__device__ float g_pprod[NCH * NCHAIN];
__device__ float g_hinit[NCH * NCHAIN];

// -------------------- GEMM C = A * B^T (64x64 tiles) --------------------
__global__ void gemm_abt(const float* __restrict__ A, const float* __restrict__ Bm,
                         float* __restrict__ C, int M, int N, int K) {
    __shared__ __align__(16) float As[32][68];
    __shared__ __align__(16) float Bs[32][68];
    int tid = threadIdx.x;
    int tx = tid & 15, ty = tid >> 4;
    int rowBase = blockIdx.y * 64;
    int colBase = blockIdx.x * 64;
    float acc[4][4];
#pragma unroll
    for (int i = 0; i < 4; i++)
#pragma unroll
        for (int j = 0; j < 4; j++) acc[i][j] = 0.f;

    for (int k0 = 0; k0 < K; k0 += 32) {
#pragma unroll
        for (int pass = 0; pass < 8; pass++) {
            int m = (tid >> 5) + pass * 8;
            int kk = tid & 31;
            As[kk][m] = A[(size_t)(rowBase + m) * K + k0 + kk];
            int nn = colBase + m;
            Bs[kk][m] = (nn < N) ? Bm[(size_t)nn * K + k0 + kk] : 0.f;
        }
        __syncthreads();
#pragma unroll
        for (int kk = 0; kk < 32; kk++) {
            float4 a4 = *reinterpret_cast<const float4*>(&As[kk][ty * 4]);
            float4 b4 = *reinterpret_cast<const float4*>(&Bs[kk][tx * 4]);
            float av[4] = {a4.x, a4.y, a4.z, a4.w};
            float bv[4] = {b4.x, b4.y, b4.z, b4.w};
#pragma unroll
            for (int i = 0; i < 4; i++)
#pragma unroll
                for (int j = 0; j < 4; j++) acc[i][j] = fmaf(av[i], bv[j], acc[i][j]);
        }
        __syncthreads();
    }
    int col = colBase + tx * 4;
    if (col < N) {
#pragma unroll
        for (int i = 0; i < 4; i++) {
            int row = rowBase + ty * 4 + i;
            *reinterpret_cast<float4*>(&C[(size_t)row * N + col]) =
                make_float4(acc[i][0], acc[i][1], acc[i][2], acc[i][3]);
        }
    }
}

// -------------------- split + transpose --------------------
__global__ void split_transpose(const float* __restrict__ xz, float* __restrict__ xraw) {
    __shared__ float s[32][33];
    int b = blockIdx.z;
    int p0 = blockIdx.x * 32;
    int d0 = blockIdx.y * 32;
    int tid = threadIdx.x;
#pragma unroll
    for (int pass = 0; pass < 4; pass++) {
        int py = (tid >> 5) + pass * 8;
        int dx = tid & 31;
        s[py][dx] = xz[((size_t)b * Lseq + p0 + py) * 192 + d0 + dx];
    }
    __syncthreads();
#pragma unroll
    for (int pass = 0; pass < 4; pass++) {
        int dy = (tid >> 5) + pass * 8;
        int px = tid & 31;
        xraw[((size_t)b * DI + d0 + dy) * Lseq + p0 + px] = s[px][dy];
    }
}

// -------------------- depthwise conv3x3 + SiLU --------------------
__global__ void conv_silu(const float* __restrict__ xraw, const float* __restrict__ cw,
                          const float* __restrict__ cb, float* __restrict__ xc,
                          float* __restrict__ xcT) {
    __shared__ float sin_[64][65];
    __shared__ float sout[64][65];
    int bd = blockIdx.x;
    int d = bd % DI;
    const float* plane = xraw + (size_t)bd * Lseq;
    int tid = threadIdx.x;
    for (int i = tid; i < 4096; i += 256) sin_[i >> 6][i & 63] = plane[i];
    float w9[9];
#pragma unroll
    for (int j = 0; j < 9; j++) w9[j] = cw[d * 9 + j];
    float bias = cb[d];
    __syncthreads();
    for (int i = tid; i < 4096; i += 256) {
        int h = i >> 6, w = i & 63;
        float acc = bias;
#pragma unroll
        for (int di = -1; di <= 1; di++) {
#pragma unroll
            for (int dj = -1; dj <= 1; dj++) {
                int hh = h + di, ww = w + dj;
                if (hh >= 0 && hh < 64 && ww >= 0 && ww < 64)
                    acc = fmaf(w9[(di + 1) * 3 + dj + 1], sin_[hh][ww], acc);
            }
        }
        float s = acc / (1.f + __expf(-acc));
        sout[h][w] = s;
        xc[(size_t)bd * Lseq + i] = s;
    }
    __syncthreads();
    for (int i = tid; i < 4096; i += 256) {
        int w = i >> 6, h = i & 63;
        xcT[(size_t)bd * Lseq + i] = sout[h][w];
    }
}

// -------------------- x_proj + dt_proj + softplus fused --------------------
#define LT 64
__device__ __forceinline__ float softplusf(float x) {
    return (x > 15.f) ? x : log1pf(__expf(x));
}

__global__ void xproj_kernel(const float* __restrict__ xc, const float* __restrict__ xcT,
                             const float* __restrict__ xpw, const float* __restrict__ dtw,
                             const float* __restrict__ dtb,
                             float* __restrict__ xbc, float* __restrict__ deltaT) {
    __shared__ float Ws[CDIM * 96];       // 14.6 KB
    __shared__ float Us[96][LT];          // 24.6 KB
    __shared__ float Dts[DTR][LT];        // 1.5 KB
    __shared__ float Wdt[96 * DTR];       // 2.3 KB
    __shared__ float Bdt[96];
    int bk = blockIdx.y;
    int b = bk >> 2, k = bk & 3;
    int l0 = blockIdx.x * LT;
    int tid = threadIdx.x;                // 256
    for (int i = tid; i < CDIM * 96; i += 256) Ws[i] = xpw[k * CDIM * 96 + i];
    for (int i = tid; i < 96 * DTR; i += 256) Wdt[i] = dtw[k * 96 * DTR + i];
    if (tid < 96) Bdt[tid] = dtb[k * 96 + tid];
    const float* src = ((k & 1) ? xcT : xc) + (size_t)b * DI * Lseq;
    bool rev = (k >= 2);
    for (int i = tid; i < 96 * LT; i += 256) {
        int e = i >> 6, li = i & 63;
        int l = l0 + li;
        Us[e][li] = src[(size_t)e * Lseq + (rev ? (Lseq - 1 - l) : l)];
    }
    __syncthreads();
    int lx = tid & 31, cy = tid >> 5;
    float acc[5][2];
#pragma unroll
    for (int j = 0; j < 5; j++) { acc[j][0] = 0.f; acc[j][1] = 0.f; }
#pragma unroll 4
    for (int e = 0; e < 96; e++) {
        float u0 = Us[e][lx];
        float u1 = Us[e][lx + 32];
#pragma unroll
        for (int j = 0; j < 5; j++) {
            int c = cy + 8 * j;
            float w = (c < CDIM) ? Ws[c * 96 + e] : 0.f;
            acc[j][0] = fmaf(w, u0, acc[j][0]);
            acc[j][1] = fmaf(w, u1, acc[j][1]);
        }
    }
#pragma unroll
    for (int j = 0; j < 5; j++) {
        int c = cy + 8 * j;
        if (c < DTR) {
            Dts[c][lx] = acc[j][0];
            Dts[c][lx + 32] = acc[j][1];
        } else if (c < CDIM) {
            xbc[((size_t)bk * Lseq + l0 + lx) * BCW + c - DTR] = acc[j][0];
            xbc[((size_t)bk * Lseq + l0 + lx + 32) * BCW + c - DTR] = acc[j][1];
        }
    }
    __syncthreads();
    // stage 2: delta[d][l] = softplus(dts . Wdt[d] + Bdt[d]), 96*64 outputs
#pragma unroll
    for (int o = 0; o < 24; o++) {
        int idx = o * 256 + tid;
        int li = idx & 63, d = idx >> 6;
        float a = Bdt[d];
#pragma unroll
        for (int r = 0; r < DTR; r++) a = fmaf(Dts[r][li], Wdt[d * DTR + r], a);
        deltaT[((size_t)bk * DI + d) * Lseq + l0 + li] = softplusf(a);
    }
}

// -------------------- chunked selective scan --------------------
// chain = bk*1536 + dp*32 + lane  (lane = hi*16 + n, d = dp*2 + hi)

__global__ void scanA_kernel(const float* __restrict__ deltaT, const float* __restrict__ xbc,
                             const float* __restrict__ xc, const float* __restrict__ xcT,
                             const float* __restrict__ A_logs,
                             float* __restrict__ hend, float* __restrict__ pprod) {
    int w = blockIdx.x * 8 + (threadIdx.x >> 5);
    int lane = threadIdx.x & 31;
    int bk = w / (48 * NCH);
    int rem = w % (48 * NCH);
    int chunk = rem / 48;
    int dp = rem % 48;
    int b = bk >> 2, k = bk & 3;
    int n = lane & 15;
    int d = dp * 2 + (lane >> 4);
    float Aval = -__expf(A_logs[(k * DI + d) * DS + n]);
    bool rev = (k >= 2);
    int l0 = chunk * CH;

    const float* drow = deltaT + ((size_t)bk * DI + d) * Lseq + l0;
    const float* xrow = xbc + ((size_t)bk * Lseq + l0) * BCW + n;
    const float* ubase = ((k & 1) ? xcT : xc) + ((size_t)b * DI + d) * Lseq;
    const float* urow = ubase + (rev ? (Lseq - 1 - l0) : l0);
    int ustep = rev ? -1 : 1;

    float h = 0.f, P = 1.f;
#pragma unroll 8
    for (int i = 0; i < CH; i++) {
        float dl = *drow;
        float uu = *urow;
        float Bv = *xrow;
        float dA = __expf(dl * Aval);
        P *= dA;
        h = fmaf(h, dA, dl * uu * Bv);
        drow += 1;
        xrow += BCW;
        urow += ustep;
    }
    int cidx = chunk * NCHAIN + bk * 1536 + dp * 32 + lane;
    hend[cidx] = h;
    pprod[cidx] = P;
}

__global__ void scanB_kernel(const float* __restrict__ hend, const float* __restrict__ pprod,
                             float* __restrict__ hinit) {
    int chain = blockIdx.x * 256 + threadIdx.x;
    float H = 0.f;
#pragma unroll 8
    for (int c = 0; c < NCH; c++) {
        int idx = c * NCHAIN + chain;
        hinit[idx] = H;
        H = fmaf(H, pprod[idx], hend[idx]);
    }
}

__global__ void scanC_kernel(const float* __restrict__ deltaT, const float* __restrict__ xbc,
                             const float* __restrict__ xc, const float* __restrict__ xcT,
                             const float* __restrict__ A_logs, const float* __restrict__ Dsp,
                             const float* __restrict__ hinit, float* __restrict__ ysd) {
    int w = blockIdx.x * 8 + (threadIdx.x >> 5);
    int lane = threadIdx.x & 31;
    int bk = w / (48 * NCH);
    int rem = w % (48 * NCH);
    int chunk = rem / 48;
    int dp = rem % 48;
    int b = bk >> 2, k = bk & 3;
    int n = lane & 15;
    int d = dp * 2 + (lane >> 4);
    float Aval = -__expf(A_logs[(k * DI + d) * DS + n]);
    float Dval = Dsp[k * DI + d];
    bool rev = (k >= 2);
    int l0 = chunk * CH;

    const float* drow = deltaT + ((size_t)bk * DI + d) * Lseq + l0;
    const float* xrow = xbc + ((size_t)bk * Lseq + l0) * BCW + n;
    const float* ubase = ((k & 1) ? xcT : xc) + ((size_t)b * DI + d) * Lseq;
    const float* urow = ubase + (rev ? (Lseq - 1 - l0) : l0);
    int ustep = rev ? -1 : 1;

    // spatial store position: p = pstart + i*pstep (maps scan index -> hw raster)
    int pstart, pstep;
    if (k == 0)      { pstart = l0;                pstep = 1;   }
    else if (k == 1) { pstart = chunk;             pstep = 64;  }
    else if (k == 2) { pstart = Lseq - 1 - l0;     pstep = -1;  }
    else             { pstart = 4032 + 63 - chunk; pstep = -64; }
    float* yrow = ysd + ((size_t)bk * DI + d) * Lseq + pstart;
    bool writer = (n == 0);

    float h = hinit[chunk * NCHAIN + bk * 1536 + dp * 32 + lane];
#pragma unroll 4
    for (int i = 0; i < CH; i++) {
        float dl = *drow;
        float uu = *urow;
        float Bv = *xrow;
        float Cv = xrow[DS];
        float dA = __expf(dl * Aval);
        h = fmaf(h, dA, dl * uu * Bv);
        float yv = h * Cv;
        yv += __shfl_xor_sync(0xffffffffu, yv, 8);
        yv += __shfl_xor_sync(0xffffffffu, yv, 4);
        yv += __shfl_xor_sync(0xffffffffu, yv, 2);
        yv += __shfl_xor_sync(0xffffffffu, yv, 1);
        if (writer) *yrow = fmaf(Dval, uu, yv);
        drow += 1;
        xrow += BCW;
        urow += ustep;
        yrow += pstep;
    }
}

// -------------------- combine 4 dirs + transpose to [p][d] --------------------
__global__ void combineT_kernel(const float* __restrict__ ysd, float* __restrict__ ycomb) {
    __shared__ float s[32][33];
    int b = blockIdx.z;
    int p0 = blockIdx.x * 32;
    int d0 = blockIdx.y * 32;
    int tid = threadIdx.x;
#pragma unroll
    for (int pass = 0; pass < 4; pass++) {
        int dd = d0 + (tid >> 5) + pass * 8;
        int px = tid & 31;
        const float* base = ysd + ((size_t)(b * 4) * DI + dd) * Lseq + p0 + px;
        float v = base[0] + base[DI * Lseq] + base[2 * DI * Lseq] + base[3 * DI * Lseq];
        s[px][(tid >> 5) + pass * 8] = v;
    }
    __syncthreads();
#pragma unroll
    for (int pass = 0; pass < 4; pass++) {
        int py = (tid >> 5) + pass * 8;
        int dx = tid & 31;
        ycomb[((size_t)b * Lseq + p0 + py) * DI + d0 + dx] = s[py][dx];
    }
}

// -------------------- LayerNorm + SiLU gate --------------------
__global__ void ln_gate_kernel(const float* __restrict__ ycomb, const float* __restrict__ xz,
                               const float* __restrict__ nw, const float* __restrict__ nb,
                               float* __restrict__ yg) {
    int ty = threadIdx.y;
    int pp = blockIdx.x * 2 + ty;
    int b = pp / Lseq, p = pp % Lseq;
    int d = threadIdx.x;
    float v = ycomb[((size_t)b * Lseq + p) * DI + d];
    __shared__ float red[2][6];
    float s1 = v, s2 = v * v;
#pragma unroll
    for (int o = 16; o >= 1; o >>= 1) {
        s1 += __shfl_xor_sync(0xffffffffu, s1, o);
        s2 += __shfl_xor_sync(0xffffffffu, s2, o);
    }
    if ((d & 31) == 0) {
        red[ty][d >> 5] = s1;
        red[ty][3 + (d >> 5)] = s2;
    }
    __syncthreads();
    float S1 = red[ty][0] + red[ty][1] + red[ty][2];
    float S2 = red[ty][3] + red[ty][4] + red[ty][5];
    float mu = S1 * (1.f / 96.f);
    float var = S2 * (1.f / 96.f) - mu * mu;
    float yn = (v - mu) * rsqrtf(var + 1e-5f) * nw[d] + nb[d];
    float zv = xz[((size_t)b * Lseq + p) * 192 + 96 + d];
    yg[((size_t)b * Lseq + p) * DI + d] = yn * (zv / (1.f + __expf(-zv)));
}

// -------------------- host launcher --------------------
extern "C" void kernel_launch(void* const* d_in, const int* in_sizes, int n_in,
                              void* d_out, int out_size) {
    const float* x     = (const float*)d_in[0];
    const float* inw   = (const float*)d_in[1];
    const float* convw = (const float*)d_in[2];
    const float* convb = (const float*)d_in[3];
    const float* xpw   = (const float*)d_in[4];
    const float* dtw   = (const float*)d_in[5];
    const float* dtb   = (const float*)d_in[6];
    const float* alog  = (const float*)d_in[7];
    const float* dsp   = (const float*)d_in[8];
    const float* nw    = (const float*)d_in[9];
    const float* nb    = (const float*)d_in[10];
    const float* ow    = (const float*)d_in[11];
    float* out = (float*)d_out;

    float *xz, *xraw, *xc, *xcT, *xbc, *deltaT, *ysd, *ycomb, *yg, *hend, *pprod, *hinit;
    cudaGetSymbolAddress((void**)&xz, g_xz);
    cudaGetSymbolAddress((void**)&xraw, g_xraw);
    cudaGetSymbolAddress((void**)&xc, g_xc);
    cudaGetSymbolAddress((void**)&xcT, g_xcT);
    cudaGetSymbolAddress((void**)&xbc, g_xbc);
    cudaGetSymbolAddress((void**)&deltaT, g_deltaT);
    cudaGetSymbolAddress((void**)&ysd, g_ysd);
    cudaGetSymbolAddress((void**)&ycomb, g_ycomb);
    cudaGetSymbolAddress((void**)&yg, g_yg);
    cudaGetSymbolAddress((void**)&hend, g_hend);
    cudaGetSymbolAddress((void**)&pprod, g_pprod);
    cudaGetSymbolAddress((void**)&hinit, g_hinit);

    gemm_abt<<<dim3(3, 256), 256>>>(x, inw, xz, Bn_ * Lseq, 192, 96);
    split_transpose<<<dim3(Lseq / 32, 3, Bn_), 256>>>(xz, xraw);
    conv_silu<<<Bn_ * DI, 256>>>(xraw, convw, convb, xc, xcT);
    xproj_kernel<<<dim3(Lseq / LT, 16), 256>>>(xc, xcT, xpw, dtw, dtb, xbc, deltaT);
    scanA_kernel<<<16 * 48 * NCH / 8, 256>>>(deltaT, xbc, xc, xcT, alog, hend, pprod);
    scanB_kernel<<<NCHAIN / 256, 256>>>(hend, pprod, hinit);
    scanC_kernel<<<16 * 48 * NCH / 8, 256>>>(deltaT, xbc, xc, xcT, alog, dsp, hinit, ysd);
    combineT_kernel<<<dim3(Lseq / 32, 3, Bn_), 256>>>(ysd, ycomb);
    ln_gate_kernel<<<(Bn_ * Lseq) / 2, dim3(96, 2)>>>(ycomb, xz, nw, nb, yg);
    gemm_abt<<<dim3(2, 256), 256>>>(yg, ow, out, Bn_ * Lseq, 96, 96);
}